// round 5
// baseline (speedup 1.0000x reference)
#include <cuda_runtime.h>
#include <math.h>
#include <stdint.h>

#define N_EMBD 1024
#define NHEAD  16
#define DH     64
#define BATCH  2
#define TSEQ   2048
#define M_TOT  (BATCH * TSEQ)   // 4096

#define PITCH   36               // smem row pitch in words (A:[m][k], B:[n][k])
#define ABUF_W  (128 * PITCH)    // 4608 words = 18432 B
#define PAIR_B  (2 * ABUF_W * 4) // 36864 B per (A,B) pair
#define GEMM_SMEM (2 * PAIR_B)   // 73728 B double-buffered

// Scratch (allocation-free rule: __device__ globals)
__device__ float g_q[BATCH * NHEAD * TSEQ * DH];
__device__ float g_k[BATCH * NHEAD * TSEQ * DH];
__device__ float g_v[BATCH * NHEAD * TSEQ * DH];
__device__ float g_att[M_TOT * N_EMBD];

__device__ __forceinline__ uint32_t f2tf32(float x) {
    uint32_t r;
    asm("cvt.rna.tf32.f32 %0, %1;" : "=r"(r) : "f"(x));
    return r;
}
__device__ __forceinline__ uint32_t smem_u32(const void* p) {
    uint32_t a;
    asm("{ .reg .u64 t; cvta.to.shared.u64 t, %1; cvt.u32.u64 %0, t; }" : "=r"(a) : "l"(p));
    return a;
}
// m16n8k8 tf32 HMMA, D += A*B (A row-major, B col-major)
__device__ __forceinline__ void mma1688(float* d, const uint32_t* a, const uint32_t* b) {
    asm volatile(
        "mma.sync.aligned.m16n8k8.row.col.f32.tf32.tf32.f32 "
        "{%0,%1,%2,%3}, {%4,%5,%6,%7}, {%8,%9}, {%0,%1,%2,%3};"
        : "+f"(d[0]), "+f"(d[1]), "+f"(d[2]), "+f"(d[3])
        : "r"(a[0]), "r"(a[1]), "r"(a[2]), "r"(a[3]), "r"(b[0]), "r"(b[1]));
}
__device__ __forceinline__ void ldsm_x4(uint32_t* r, uint32_t addr) {
    asm volatile("ldmatrix.sync.aligned.m8n8.x4.shared.b16 {%0,%1,%2,%3}, [%4];"
        : "=r"(r[0]), "=r"(r[1]), "=r"(r[2]), "=r"(r[3]) : "r"(addr));
}
// fast exp: FMA/ALU pipes only; exact 0 for x<=-80 (incl -inf)
__device__ __forceinline__ float fexp(float x) {
    const float L2E = 1.4426950408889634f;
    float t = fmaf(x, L2E, 12582912.0f);
    float i = t - 12582912.0f;
    float f = fmaf(x, L2E, -i);
    float p =            1.3333434e-3f;
    p = fmaf(p, f, 9.6181291e-3f);
    p = fmaf(p, f, 5.5504108e-2f);
    p = fmaf(p, f, 2.4022651e-1f);
    p = fmaf(p, f, 6.9314718e-1f);
    p = fmaf(p, f, 1.0f);
    int e = __float_as_int(t) - 0x4B400000;
    int r = __float_as_int(p) + (e << 23);
    return (x > -80.0f) ? __int_as_float(r) : 0.0f;
}

// ---------------------------------------------------------------------------
// Double-buffered, ldmatrix-based tf32 GEMM core. CTA 128x128, K-chunk 32,
// 8 warps (2m x 4n), 1 CTA/SM (full pipeline hides latency).
// sA: [m][k] pitch 36; sB: [n][k] pitch 36 — both ldmatrix-clean.
// ---------------------------------------------------------------------------
struct GemmCtx {
    // A loader
    const float* aSrc;   // &X[(rm+am)*N_EMBD + ac4*4], advance by k0
    // B loader: per thread one n, 16 k's (4 units of 4)
    const float* bSrc;   // base pointer for this thread's n column
    int bStrideK;        // element stride per k step
    int nB, t7;
};

__device__ __forceinline__ void gemm_pipeline(
    uint32_t smemBase, const GemmCtx& ctx, float acc[4][4][4],
    int tid, int wid, int lane)
{
    const int am  = tid >> 3;      // A-load row base
    const int wm  = wid >> 2;
    const int wn  = wid & 3;

    const uint32_t lmA0 = ((wm * 64 + (lane & 15)) * PITCH + ((lane >> 4) & 1) * 4) * 4;
    const uint32_t lmB0 = (((wn * 32 + (lane & 7) + ((lane >> 4) & 1) * 8)) * PITCH
                           + ((lane >> 3) & 1) * 4) * 4;

    float4 rA[4];
    float  rB[4][4];

    // prologue: chunk 0
#pragma unroll
    for (int i = 0; i < 4; i++)
        rA[i] = *(const float4*)(ctx.aSrc + (size_t)i * 32 * N_EMBD);
#pragma unroll
    for (int u = 0; u < 4; u++)
#pragma unroll
        for (int kk = 0; kk < 4; kk++)
            rB[u][kk] = ctx.bSrc[(size_t)(ctx.t7 * 4 + u * 8 + kk) * ctx.bStrideK];

    for (int c = 0; c < 32; c++) {
        const uint32_t aA = smemBase + (uint32_t)(c & 1) * PAIR_B;
        const uint32_t aB = aA + ABUF_W * 4;
        // store staged chunk c
        {
            uint32_t* sA = (uint32_t*)((char*)0 + 0); // unused; use addr arithmetic below
            (void)sA;
        }
#pragma unroll
        for (int i = 0; i < 4; i++) {
            uint4 t;
            t.x = f2tf32(rA[i].x); t.y = f2tf32(rA[i].y);
            t.z = f2tf32(rA[i].z); t.w = f2tf32(rA[i].w);
            uint32_t addr = aA + ((uint32_t)(am + i * 32) * PITCH + (uint32_t)(tid & 7) * 4) * 4;
            asm volatile("st.shared.v4.b32 [%0], {%1,%2,%3,%4};"
                :: "r"(addr), "r"(t.x), "r"(t.y), "r"(t.z), "r"(t.w) : "memory");
        }
#pragma unroll
        for (int u = 0; u < 4; u++) {
            uint4 t;
            t.x = f2tf32(rB[u][0]); t.y = f2tf32(rB[u][1]);
            t.z = f2tf32(rB[u][2]); t.w = f2tf32(rB[u][3]);
            uint32_t addr = aB + ((uint32_t)ctx.nB * PITCH + (uint32_t)(ctx.t7 * 4 + u * 8)) * 4;
            asm volatile("st.shared.v4.b32 [%0], {%1,%2,%3,%4};"
                :: "r"(addr), "r"(t.x), "r"(t.y), "r"(t.z), "r"(t.w) : "memory");
        }
        __syncthreads();

        // issue next chunk's global loads (consumed after compute)
        if (c < 31) {
            const int k0 = (c + 1) * 32;
#pragma unroll
            for (int i = 0; i < 4; i++)
                rA[i] = *(const float4*)(ctx.aSrc + k0 + (size_t)i * 32 * N_EMBD);
#pragma unroll
            for (int u = 0; u < 4; u++)
#pragma unroll
                for (int kk = 0; kk < 4; kk++)
                    rB[u][kk] = ctx.bSrc[(size_t)(k0 + ctx.t7 * 4 + u * 8 + kk) * ctx.bStrideK];
        }

        // compute on buffer c
        const uint32_t lmA = aA + lmA0;
        const uint32_t lmB = aB + lmB0;
#pragma unroll
        for (int kb = 0; kb < 4; kb++) {
            uint32_t a[4][4], b[4][2], t[4];
#pragma unroll
            for (int i = 0; i < 4; i++)
                ldsm_x4(a[i], lmA + (uint32_t)(i * 16 * PITCH + kb * 8) * 4);
            ldsm_x4(t, lmB + (uint32_t)(kb * 8) * 4);
            b[0][0] = t[0]; b[0][1] = t[1]; b[1][0] = t[2]; b[1][1] = t[3];
            ldsm_x4(t, lmB + (uint32_t)(16 * PITCH + kb * 8) * 4);
            b[2][0] = t[0]; b[2][1] = t[1]; b[3][0] = t[2]; b[3][1] = t[3];
#pragma unroll
            for (int i = 0; i < 4; i++)
#pragma unroll
                for (int j = 0; j < 4; j++)
                    mma1688(acc[i][j], a[i], b[j]);
        }
        __syncthreads();
    }
}

__global__ __launch_bounds__(256, 1) void qkv_mma(
    const float* __restrict__ X,
    const float* __restrict__ Wq,
    const float* __restrict__ Wk,
    const float* __restrict__ Wv)
{
    extern __shared__ __align__(16) uint32_t smem[];
    const int tid = threadIdx.x;
    const int wid = tid >> 5, lane = tid & 31;
    const int cn = blockIdx.x * 128;
    const int rm = blockIdx.y * 128;
    const int which = cn >> 10;
    const int cnn = cn & 1023;
    const float* W = (which == 0) ? Wq : (which == 1) ? Wk : Wv;
    float* OUT     = (which == 0) ? g_q : (which == 1) ? g_k : g_v;

    GemmCtx ctx;
    ctx.aSrc = X + (size_t)(rm + (tid >> 3)) * N_EMBD + (tid & 7) * 4;
    ctx.nB = tid & 127;
    ctx.t7 = tid >> 7;
    {
        const int cg = cnn + ctx.nB;
        ctx.bSrc = W + (size_t)(cg >> 6) * (N_EMBD * DH) + (cg & 63);
        ctx.bStrideK = DH;
    }

    float acc[4][4][4] = {};
    gemm_pipeline(smem_u32(smem), ctx, acc, tid, wid, lane);

    const int wm = wid >> 2, wn = wid & 3;
    const int lr = lane >> 2, lc = lane & 3;
#pragma unroll
    for (int i = 0; i < 4; i++) {
        const int r0 = rm + wm * 64 + i * 16 + lr;
        const int bb = r0 >> 11;
        const int tt = r0 & (TSEQ - 1);
#pragma unroll
        for (int j = 0; j < 4; j++) {
            const int cg = cnn + wn * 32 + j * 8 + 2 * lc;
            const int hh = cg >> 6, dd = cg & 63;
            float* base = OUT + (((size_t)(bb * NHEAD + hh)) * TSEQ + tt) * DH + dd;
            float2 v0 = {acc[i][j][0], acc[i][j][1]};
            float2 v1 = {acc[i][j][2], acc[i][j][3]};
            *(float2*)base = v0;
            *(float2*)(base + 8 * DH) = v1;
        }
    }
}

__global__ __launch_bounds__(256, 1) void proj_mma(
    const float* __restrict__ Wp,
    const float* __restrict__ Bp,
    float* __restrict__ OUTP)
{
    extern __shared__ __align__(16) uint32_t smem[];
    const int tid = threadIdx.x;
    const int wid = tid >> 5, lane = tid & 31;
    const int cn = blockIdx.x * 128;
    const int rm = blockIdx.y * 128;

    GemmCtx ctx;
    ctx.aSrc = g_att + (size_t)(rm + (tid >> 3)) * N_EMBD + (tid & 7) * 4;
    ctx.nB = tid & 127;
    ctx.t7 = tid >> 7;
    ctx.bSrc = Wp + cn + ctx.nB;
    ctx.bStrideK = N_EMBD;

    float acc[4][4][4] = {};
    gemm_pipeline(smem_u32(smem), ctx, acc, tid, wid, lane);

    const int wm = wid >> 2, wn = wid & 3;
    const int lr = lane >> 2, lc = lane & 3;
#pragma unroll
    for (int i = 0; i < 4; i++) {
        const int r0 = rm + wm * 64 + i * 16 + lr;
#pragma unroll
        for (int j = 0; j < 4; j++) {
            const int cg = cn + wn * 32 + j * 8 + 2 * lc;
            float2 bv = *(const float2*)(Bp + cg);
            float2 v0 = {acc[i][j][0] + bv.x, acc[i][j][1] + bv.y};
            float2 v1 = {acc[i][j][2] + bv.x, acc[i][j][3] + bv.y};
            *(float2*)(OUTP + (size_t)r0 * N_EMBD + cg) = v0;
            *(float2*)(OUTP + (size_t)(r0 + 8) * N_EMBD + cg) = v1;
        }
    }
}

// ---------------------------------------------------------------------------
// Causal flash attention on tf32 mma.sync. 128 Q-rows per CTA (8 warps),
// KV tiles of 64 — halves KV traffic vs 64-row CTAs.
// ---------------------------------------------------------------------------
__global__ __launch_bounds__(256, 2) void flash_mma()
{
    __shared__ __align__(16) uint32_t Ks[64 * 68];
    __shared__ __align__(16) uint32_t Vs[64 * 68];

    const int tid  = threadIdx.x;
    const int wid  = tid >> 5;          // 0..7
    const int lane = tid & 31;
    const int g    = lane >> 2;
    const int tig  = lane & 3;
    const int bi   = (int)gridDim.x - 1 - (int)blockIdx.x;   // heavy first
    const int bh   = blockIdx.y;
    const int m0   = bi * 128;

    const float* Qb = g_q + (size_t)bh * TSEQ * DH;
    const float* Kb = g_k + (size_t)bh * TSEQ * DH;
    const float* Vb = g_v + (size_t)bh * TSEQ * DH;

    const int rl0 = wid * 16 + g;       // 0..127
    const int rl1 = rl0 + 8;
    const float scale = 0.03125f;       // 1024^-0.5 folded into Q

    uint32_t qf[8][4];
#pragma unroll
    for (int kb = 0; kb < 8; kb++) {
        const float* q0 = Qb + (size_t)(m0 + rl0) * DH + kb * 8 + tig;
        const float* q1 = Qb + (size_t)(m0 + rl1) * DH + kb * 8 + tig;
        qf[kb][0] = f2tf32(q0[0] * scale);
        qf[kb][1] = f2tf32(q1[0] * scale);
        qf[kb][2] = f2tf32(q0[4] * scale);
        qf[kb][3] = f2tf32(q1[4] * scale);
    }

    float oacc[8][4] = {};
    float mr0 = -INFINITY, mr1 = -INFINITY, l0 = 0.0f, l1 = 0.0f;

    const int ntiles = 2 * bi + 2;
    for (int jt = 0; jt < ntiles; jt++) {
        const int n0 = jt * 64;
        __syncthreads();
#pragma unroll
        for (int i = 0; i < 4; i++) {
            const int e  = tid + i * 256;
            const int s  = e >> 4;
            const int d0 = (e & 15) * 4;
            float4 kv = *(const float4*)(Kb + (size_t)(n0 + s) * DH + d0);
            uint4 tk;
            tk.x = f2tf32(kv.x); tk.y = f2tf32(kv.y); tk.z = f2tf32(kv.z); tk.w = f2tf32(kv.w);
            *(uint4*)&Ks[s * 68 + d0] = tk;
            float4 vv = *(const float4*)(Vb + (size_t)(n0 + s) * DH + d0);
            uint4 tv;
            tv.x = f2tf32(vv.x); tv.y = f2tf32(vv.y); tv.z = f2tf32(vv.z); tv.w = f2tf32(vv.w);
            *(uint4*)&Vs[s * 68 + d0] = tv;
        }
        __syncthreads();

        float sacc[8][4] = {};
#pragma unroll
        for (int kb = 0; kb < 8; kb++) {
            uint32_t b[8][2];
#pragma unroll
            for (int j = 0; j < 8; j++) {
                const int srow = (j * 8 + g) * 68 + kb * 8 + tig;
                b[j][0] = Ks[srow];
                b[j][1] = Ks[srow + 4];
            }
#pragma unroll
            for (int j = 0; j < 8; j++)
                mma1688(sacc[j], qf[kb], b[j]);
        }

        // causal mask whenever this tile can cross the diagonal for this warp
        if (n0 + 63 > m0 + wid * 16) {
            const int grow0 = m0 + rl0;
            const int grow1 = m0 + rl1;
#pragma unroll
            for (int j = 0; j < 8; j++) {
                const int gcol = n0 + j * 8 + 2 * tig;
                if (gcol     > grow0) sacc[j][0] = -INFINITY;
                if (gcol + 1 > grow0) sacc[j][1] = -INFINITY;
                if (gcol     > grow1) sacc[j][2] = -INFINITY;
                if (gcol + 1 > grow1) sacc[j][3] = -INFINITY;
            }
        }

        float mt0 = -INFINITY, mt1 = -INFINITY;
#pragma unroll
        for (int j = 0; j < 8; j++) {
            mt0 = fmaxf(mt0, fmaxf(sacc[j][0], sacc[j][1]));
            mt1 = fmaxf(mt1, fmaxf(sacc[j][2], sacc[j][3]));
        }
        mt0 = fmaxf(mt0, __shfl_xor_sync(0xffffffffu, mt0, 1));
        mt0 = fmaxf(mt0, __shfl_xor_sync(0xffffffffu, mt0, 2));
        mt1 = fmaxf(mt1, __shfl_xor_sync(0xffffffffu, mt1, 1));
        mt1 = fmaxf(mt1, __shfl_xor_sync(0xffffffffu, mt1, 2));

        const float mn0 = fmaxf(mr0, mt0);
        const float mn1 = fmaxf(mr1, mt1);
        const float al0 = fexp(mr0 - mn0);
        const float al1 = fexp(mr1 - mn1);
        mr0 = mn0; mr1 = mn1;

        float rs0 = 0.0f, rs1 = 0.0f;
        uint32_t pf[8][4];
        const int srcA = (lane & 28) | (tig >> 1);
        const bool odd = (tig & 1);
#pragma unroll
        for (int j = 0; j < 8; j++) {
            const float p0 = fexp(sacc[j][0] - mn0);
            const float p1 = fexp(sacc[j][1] - mn0);
            const float p2 = fexp(sacc[j][2] - mn1);
            const float p3 = fexp(sacc[j][3] - mn1);
            rs0 += p0 + p1;
            rs1 += p2 + p3;
            const uint32_t u0 = f2tf32(p0), u1 = f2tf32(p1);
            const uint32_t u2 = f2tf32(p2), u3 = f2tf32(p3);
            uint32_t x0 = __shfl_sync(0xffffffffu, u0, srcA);
            uint32_t x1 = __shfl_sync(0xffffffffu, u1, srcA);
            uint32_t y0 = __shfl_sync(0xffffffffu, u0, srcA + 2);
            uint32_t y1 = __shfl_sync(0xffffffffu, u1, srcA + 2);
            uint32_t x2 = __shfl_sync(0xffffffffu, u2, srcA);
            uint32_t x3 = __shfl_sync(0xffffffffu, u3, srcA);
            uint32_t y2 = __shfl_sync(0xffffffffu, u2, srcA + 2);
            uint32_t y3 = __shfl_sync(0xffffffffu, u3, srcA + 2);
            pf[j][0] = odd ? x1 : x0;
            pf[j][2] = odd ? y1 : y0;
            pf[j][1] = odd ? x3 : x2;
            pf[j][3] = odd ? y3 : y2;
        }
        rs0 += __shfl_xor_sync(0xffffffffu, rs0, 1);
        rs0 += __shfl_xor_sync(0xffffffffu, rs0, 2);
        rs1 += __shfl_xor_sync(0xffffffffu, rs1, 1);
        rs1 += __shfl_xor_sync(0xffffffffu, rs1, 2);
        l0 = l0 * al0 + rs0;
        l1 = l1 * al1 + rs1;
#pragma unroll
        for (int j = 0; j < 8; j++) {
            oacc[j][0] *= al0; oacc[j][1] *= al0;
            oacc[j][2] *= al1; oacc[j][3] *= al1;
        }

#pragma unroll
        for (int kb = 0; kb < 8; kb++) {
            uint32_t b[8][2];
#pragma unroll
            for (int j = 0; j < 8; j++) {
                const int srow = (kb * 8 + tig) * 68 + j * 8 + g;
                b[j][0] = Vs[srow];
                b[j][1] = Vs[srow + 4 * 68];
            }
#pragma unroll
            for (int j = 0; j < 8; j++)
                mma1688(oacc[j], pf[kb], b[j]);
        }
    }

    const float rl0f = 1.0f / l0;
    const float rl1f = 1.0f / l1;
    const int bb = bh >> 4;
    const int hh = bh & 15;
    const size_t row0 = (size_t)bb * TSEQ + (m0 + rl0);
    const size_t row1 = (size_t)bb * TSEQ + (m0 + rl1);
#pragma unroll
    for (int j = 0; j < 8; j++) {
        const int col = hh * DH + j * 8 + 2 * tig;
        float2 v0 = {oacc[j][0] * rl0f, oacc[j][1] * rl0f};
        float2 v1 = {oacc[j][2] * rl1f, oacc[j][3] * rl1f};
        *(float2*)(g_att + row0 * N_EMBD + col) = v0;
        *(float2*)(g_att + row1 * N_EMBD + col) = v1;
    }
}

extern "C" void kernel_launch(void* const* d_in, const int* in_sizes, int n_in,
                              void* d_out, int out_size)
{
    const float* x  = (const float*)d_in[0];
    const float* wq = (const float*)d_in[1];
    const float* wk = (const float*)d_in[2];
    const float* wv = (const float*)d_in[3];
    const float* wp = (const float*)d_in[4];
    const float* bp = (const float*)d_in[5];
    float* out = (float*)d_out;

    cudaFuncSetAttribute(qkv_mma,  cudaFuncAttributeMaxDynamicSharedMemorySize, GEMM_SMEM);
    cudaFuncSetAttribute(proj_mma, cudaFuncAttributeMaxDynamicSharedMemorySize, GEMM_SMEM);

    qkv_mma<<<dim3(3072 / 128, M_TOT / 128), 256, GEMM_SMEM>>>(x, wq, wk, wv);
    flash_mma<<<dim3(TSEQ / 128, BATCH * NHEAD), 256>>>();
    proj_mma<<<dim3(N_EMBD / 128, M_TOT / 128), 256, GEMM_SMEM>>>(wp, bp, out);
}

// round 6
// speedup vs baseline: 1.1396x; 1.1396x over previous
#include <cuda_runtime.h>
#include <math.h>
#include <stdint.h>

#define N_EMBD 1024
#define NHEAD  16
#define DH     64
#define BATCH  2
#define TSEQ   2048
#define M_TOT  (BATCH * TSEQ)   // 4096

// GEMM smem geometry (words)
#define G_AW 4608                 // A stage: 128 rows * pitch 36
#define G_BW 4224                 // B stage: 32 k * pitch 132
#define G_SW (G_AW + G_BW)        // 8832 words = 35328 B / stage
#define G_SMEM (G_SW * 4 * 3)     // 3 stages = 105984 B

// Flash smem geometry (words)
#define F_KW (64 * 68)            // 4352 words per K (or V) tile
#define F_SW (2 * F_KW)           // 8704 words per stage (K+V)
#define F_SMEM (F_SW * 4 * 2)     // 2 stages = 69632 B

// Scratch (allocation-free rule: __device__ globals)
__device__ float g_q[BATCH * NHEAD * TSEQ * DH];
__device__ float g_k[BATCH * NHEAD * TSEQ * DH];
__device__ float g_v[BATCH * NHEAD * TSEQ * DH];
__device__ float g_att[M_TOT * N_EMBD];
// tf32-pre-rounded copies of inputs
__device__ float g_xr[M_TOT * N_EMBD];
__device__ float g_wqr[NHEAD * N_EMBD * DH];
__device__ float g_wkr[NHEAD * N_EMBD * DH];
__device__ float g_wvr[NHEAD * N_EMBD * DH];
__device__ float g_wpr[N_EMBD * N_EMBD];

__device__ __forceinline__ uint32_t f2tf32(float x) {
    uint32_t r;
    asm("cvt.rna.tf32.f32 %0, %1;" : "=r"(r) : "f"(x));
    return r;
}
__device__ __forceinline__ float rtf(float x) { return __uint_as_float(f2tf32(x)); }

__device__ __forceinline__ uint32_t smem_u32(const void* p) {
    uint32_t a;
    asm("{ .reg .u64 t; cvta.to.shared.u64 t, %1; cvt.u32.u64 %0, t; }" : "=r"(a) : "l"(p));
    return a;
}
__device__ __forceinline__ void cp16(uint32_t dst, const void* src) {
    asm volatile("{ .reg .u64 g; cvta.to.global.u64 g, %1; cp.async.cg.shared.global [%0], [g], 16; }"
        :: "r"(dst), "l"(src) : "memory");
}
#define CP_COMMIT() asm volatile("cp.async.commit_group;" ::: "memory")
#define CP_WAIT1()  asm volatile("cp.async.wait_group 1;" ::: "memory")

// m16n8k8 tf32 HMMA, D += A*B (A row-major, B col-major)
__device__ __forceinline__ void mma1688(float* d, const uint32_t* a, const uint32_t* b) {
    asm volatile(
        "mma.sync.aligned.m16n8k8.row.col.f32.tf32.tf32.f32 "
        "{%0,%1,%2,%3}, {%4,%5,%6,%7}, {%8,%9}, {%0,%1,%2,%3};"
        : "+f"(d[0]), "+f"(d[1]), "+f"(d[2]), "+f"(d[3])
        : "r"(a[0]), "r"(a[1]), "r"(a[2]), "r"(a[3]), "r"(b[0]), "r"(b[1]));
}

// fast exp: FMA/ALU pipes only; exact 0 for x<=-80 (incl -inf)
__device__ __forceinline__ float fexp(float x) {
    const float L2E = 1.4426950408889634f;
    float t = fmaf(x, L2E, 12582912.0f);
    float i = t - 12582912.0f;
    float f = fmaf(x, L2E, -i);
    float p =            1.3333434e-3f;
    p = fmaf(p, f, 9.6181291e-3f);
    p = fmaf(p, f, 5.5504108e-2f);
    p = fmaf(p, f, 2.4022651e-1f);
    p = fmaf(p, f, 6.9314718e-1f);
    p = fmaf(p, f, 1.0f);
    int e = __float_as_int(t) - 0x4B400000;
    int r = __float_as_int(p) + (e << 23);
    return (x > -80.0f) ? __int_as_float(r) : 0.0f;
}

// ---------------------------------------------------------------------------
// Pre-round inputs to tf32 (rna) so GEMMs can cp.async raw bytes.
// which: 0=x 1=wq 2=wk 3=wv 4=wp
// ---------------------------------------------------------------------------
__global__ void round_tf32_k(const float4* __restrict__ src, int which, int n4)
{
    float* dsts[5] = {g_xr, g_wqr, g_wkr, g_wvr, g_wpr};
    float4* dst = (float4*)dsts[which];
    const int i = blockIdx.x * blockDim.x + threadIdx.x;
    if (i < n4) {
        float4 v = src[i];
        float4 o;
        o.x = rtf(v.x); o.y = rtf(v.y); o.z = rtf(v.z); o.w = rtf(v.w);
        dst[i] = o;
    }
}

// ---------------------------------------------------------------------------
// cp.async issue for GEMM stage: A 128x32 ([m][k] pitch 36), B 32x128 ([k][n] pitch 132)
// ---------------------------------------------------------------------------
__device__ __forceinline__ void gemm_issue(uint32_t smembase, int buf, int k0,
    const float* Abase, const float* Bcol, int bstride, int tid)
{
    const uint32_t bw = (uint32_t)buf * G_SW;
    const int ar = tid >> 3, as = tid & 7;
#pragma unroll
    for (int i = 0; i < 8; i++) {
        const int row = ar + 16 * i;
        cp16(smembase + (bw + row * 36 + as * 4) * 4,
             Abase + (size_t)row * N_EMBD + k0 + as * 4);
    }
    const int bk = tid >> 5;
    const int n4 = (tid & 31) * 4;
#pragma unroll
    for (int i = 0; i < 8; i++) {
        const int k = bk + 4 * i;
        cp16(smembase + (bw + G_AW + k * 132 + n4) * 4,
             Bcol + (size_t)(k0 + k) * bstride);
    }
}

// GEMM compute on one stage: 4 warps, warp tile 64x64
__device__ __forceinline__ void gemm_compute(const uint32_t* sA, const uint32_t* sB,
    float acc[4][8][4], int wm, int wn, int lr, int lc)
{
#pragma unroll
    for (int kb = 0; kb < 4; kb++) {
        const int ka = kb * 8 + lc;
        uint32_t a[4][4], b[8][2];
#pragma unroll
        for (int i = 0; i < 4; i++) {
            const int mr = wm * 64 + i * 16 + lr;
            a[i][0] = sA[mr * 36 + ka];
            a[i][1] = sA[(mr + 8) * 36 + ka];
            a[i][2] = sA[mr * 36 + ka + 4];
            a[i][3] = sA[(mr + 8) * 36 + ka + 4];
        }
#pragma unroll
        for (int j = 0; j < 8; j++) {
            const int nn = wn * 64 + j * 8 + lr;
            b[j][0] = sB[ka * 132 + nn];
            b[j][1] = sB[(ka + 4) * 132 + nn];
        }
#pragma unroll
        for (int i = 0; i < 4; i++)
#pragma unroll
            for (int j = 0; j < 8; j++)
                mma1688(acc[i][j], a[i], b[j]);
    }
}

__global__ __launch_bounds__(128, 2) void qkv_mma()
{
    extern __shared__ uint32_t smem[];
    const uint32_t smembase = smem_u32(smem);
    const int tid = threadIdx.x;
    const int wid = tid >> 5, lane = tid & 31;
    const int wm = wid >> 1, wn = wid & 1;
    const int lr = lane >> 2, lc = lane & 3;
    const int cn = blockIdx.x * 128, rm = blockIdx.y * 128;
    const int which = cn >> 10;
    const int cnn = cn & 1023;
    const float* W = (which == 0) ? g_wqr : (which == 1) ? g_wkr : g_wvr;
    float* OUT     = (which == 0) ? g_q  : (which == 1) ? g_k  : g_v;

    const float* Abase = g_xr + (size_t)rm * N_EMBD;
    const int n4c = (tid & 31) * 4;
    const int cg0 = cnn + n4c;
    const float* Bcol = W + (size_t)(cg0 >> 6) * (N_EMBD * DH) + (cg0 & 63);

    gemm_issue(smembase, 0, 0,  Abase, Bcol, DH, tid); CP_COMMIT();
    gemm_issue(smembase, 1, 32, Abase, Bcol, DH, tid); CP_COMMIT();

    float acc[4][8][4] = {};
    for (int c = 0; c < 32; c++) {
        CP_WAIT1();
        __syncthreads();
        if (c + 2 < 32) gemm_issue(smembase, (c + 2) % 3, (c + 2) * 32, Abase, Bcol, DH, tid);
        CP_COMMIT();
        const uint32_t* sA = smem + (c % 3) * G_SW;
        gemm_compute(sA, sA + G_AW, acc, wm, wn, lr, lc);
    }

    // store tf32-rounded q/k/v in (B,H,T,Dh)
#pragma unroll
    for (int i = 0; i < 4; i++) {
        const int r0 = rm + wm * 64 + i * 16 + lr;
        const int bb = r0 >> 11, tt = r0 & (TSEQ - 1);
#pragma unroll
        for (int j = 0; j < 8; j++) {
            const int cg = cnn + wn * 64 + j * 8 + 2 * lc;
            const int hh = cg >> 6, dd = cg & 63;
            float* base = OUT + (((size_t)(bb * NHEAD + hh)) * TSEQ + tt) * DH + dd;
            float2 v0 = {rtf(acc[i][j][0]), rtf(acc[i][j][1])};
            float2 v1 = {rtf(acc[i][j][2]), rtf(acc[i][j][3])};
            *(float2*)base = v0;
            *(float2*)(base + 8 * DH) = v1;
        }
    }
}

__global__ __launch_bounds__(128, 2) void proj_mma(
    const float* __restrict__ Bp, float* __restrict__ OUTP)
{
    extern __shared__ uint32_t smem[];
    const uint32_t smembase = smem_u32(smem);
    const int tid = threadIdx.x;
    const int wid = tid >> 5, lane = tid & 31;
    const int wm = wid >> 1, wn = wid & 1;
    const int lr = lane >> 2, lc = lane & 3;
    const int cn = blockIdx.x * 128, rm = blockIdx.y * 128;

    const float* Abase = g_att + (size_t)rm * N_EMBD;
    const float* Bcol = g_wpr + cn + (tid & 31) * 4;

    gemm_issue(smembase, 0, 0,  Abase, Bcol, N_EMBD, tid); CP_COMMIT();
    gemm_issue(smembase, 1, 32, Abase, Bcol, N_EMBD, tid); CP_COMMIT();

    float acc[4][8][4] = {};
    for (int c = 0; c < 32; c++) {
        CP_WAIT1();
        __syncthreads();
        if (c + 2 < 32) gemm_issue(smembase, (c + 2) % 3, (c + 2) * 32, Abase, Bcol, N_EMBD, tid);
        CP_COMMIT();
        const uint32_t* sA = smem + (c % 3) * G_SW;
        gemm_compute(sA, sA + G_AW, acc, wm, wn, lr, lc);
    }

#pragma unroll
    for (int i = 0; i < 4; i++) {
        const int r0 = rm + wm * 64 + i * 16 + lr;
#pragma unroll
        for (int j = 0; j < 8; j++) {
            const int cg = cn + wn * 64 + j * 8 + 2 * lc;
            float2 bv = *(const float2*)(Bp + cg);
            float2 v0 = {acc[i][j][0] + bv.x, acc[i][j][1] + bv.y};
            float2 v1 = {acc[i][j][2] + bv.x, acc[i][j][3] + bv.y};
            *(float2*)(OUTP + (size_t)r0 * N_EMBD + cg) = v0;
            *(float2*)(OUTP + (size_t)(r0 + 8) * N_EMBD + cg) = v1;
        }
    }
}

// ---------------------------------------------------------------------------
// Causal flash attention, tf32 mma.sync. 128 threads / 4 warps; warp owns
// 32 Q-rows (2 row-blocks of 16) -> K/V fragments loaded once serve both.
// cp.async double-buffered K/V tiles of 64. Warps skip fully-masked tiles.
// ---------------------------------------------------------------------------
__device__ __forceinline__ void flash_issue(uint32_t smembase,
    const float* Kb, const float* Vb, int tid, int jt)
{
    const int n0 = jt * 64;
    const uint32_t bw = (uint32_t)(jt & 1) * F_SW;
#pragma unroll
    for (int i = 0; i < 8; i++) {
        const int e = tid + i * 128;
        const int s = e >> 4;
        const int d4 = (e & 15) * 4;
        cp16(smembase + (bw + s * 68 + d4) * 4,        Kb + (size_t)(n0 + s) * DH + d4);
        cp16(smembase + (bw + F_KW + s * 68 + d4) * 4, Vb + (size_t)(n0 + s) * DH + d4);
    }
}

__global__ __launch_bounds__(128, 2) void flash_mma()
{
    extern __shared__ uint32_t smem[];
    const uint32_t smembase = smem_u32(smem);
    const int tid  = threadIdx.x;
    const int wid  = tid >> 5;          // 0..3
    const int lane = tid & 31;
    const int g    = lane >> 2;
    const int tig  = lane & 3;
    const int bi   = (int)gridDim.x - 1 - (int)blockIdx.x;   // heavy first
    const int bh   = blockIdx.y;
    const int m0   = bi * 128;

    const float* Qb = g_q + (size_t)bh * TSEQ * DH;
    const float* Kb = g_k + (size_t)bh * TSEQ * DH;
    const float* Vb = g_v + (size_t)bh * TSEQ * DH;

    const float scale = 0.03125f;       // 2^-5: exact on tf32 values

    // Q fragments for 2 row-blocks, resident whole kernel (values pre-rounded)
    uint32_t qf[2][8][4];
#pragma unroll
    for (int rb = 0; rb < 2; rb++) {
        const int rl0 = wid * 32 + rb * 16 + g;
        const int rl1 = rl0 + 8;
#pragma unroll
        for (int kb = 0; kb < 8; kb++) {
            const float* q0 = Qb + (size_t)(m0 + rl0) * DH + kb * 8 + tig;
            const float* q1 = Qb + (size_t)(m0 + rl1) * DH + kb * 8 + tig;
            qf[rb][kb][0] = __float_as_uint(q0[0] * scale);
            qf[rb][kb][1] = __float_as_uint(q1[0] * scale);
            qf[rb][kb][2] = __float_as_uint(q0[4] * scale);
            qf[rb][kb][3] = __float_as_uint(q1[4] * scale);
        }
    }

    float oacc[2][8][4] = {};
    float mrow[2][2], lrow[2][2];
#pragma unroll
    for (int rb = 0; rb < 2; rb++) {
        mrow[rb][0] = -INFINITY; mrow[rb][1] = -INFINITY;
        lrow[rb][0] = 0.0f;      lrow[rb][1] = 0.0f;
    }

    flash_issue(smembase, Kb, Vb, tid, 0); CP_COMMIT();

    const int ntiles = 2 * bi + 2;
    for (int jt = 0; jt < ntiles; jt++) {
        __syncthreads();                 // prev compute done before reusing buffer
        if (jt + 1 < ntiles) flash_issue(smembase, Kb, Vb, tid, jt + 1);
        CP_COMMIT();
        CP_WAIT1();
        __syncthreads();

        const uint32_t* Ks = smem + (jt & 1) * F_SW;
        const uint32_t* Vs = Ks + F_KW;
        const int n0 = jt * 64;
        const bool active = (n0 <= m0 + wid * 32 + 31);
        if (active) {
            // S = Qscaled * K^T
            float sacc[2][8][4] = {};
#pragma unroll
            for (int kb = 0; kb < 8; kb++) {
                uint32_t b[8][2];
#pragma unroll
                for (int j = 0; j < 8; j++) {
                    const int srow = (j * 8 + g) * 68 + kb * 8 + tig;
                    b[j][0] = Ks[srow];
                    b[j][1] = Ks[srow + 4];
                }
#pragma unroll
                for (int rb = 0; rb < 2; rb++)
#pragma unroll
                    for (int j = 0; j < 8; j++)
                        mma1688(sacc[rb][j], qf[rb][kb], b[j]);
            }

            // causal mask
#pragma unroll
            for (int rb = 0; rb < 2; rb++) {
                if (n0 + 63 > m0 + wid * 32 + rb * 16) {
                    const int grow0 = m0 + wid * 32 + rb * 16 + g;
                    const int grow1 = grow0 + 8;
#pragma unroll
                    for (int j = 0; j < 8; j++) {
                        const int gcol = n0 + j * 8 + 2 * tig;
                        if (gcol     > grow0) sacc[rb][j][0] = -INFINITY;
                        if (gcol + 1 > grow0) sacc[rb][j][1] = -INFINITY;
                        if (gcol     > grow1) sacc[rb][j][2] = -INFINITY;
                        if (gcol + 1 > grow1) sacc[rb][j][3] = -INFINITY;
                    }
                }
            }

            // online softmax per row-block; build P fragments (C->A layout shuffles)
            uint32_t pf[2][8][4];
            const int srcA = (lane & 28) | (tig >> 1);
            const bool odd = (tig & 1);
#pragma unroll
            for (int rb = 0; rb < 2; rb++) {
                float mt0 = -INFINITY, mt1 = -INFINITY;
#pragma unroll
                for (int j = 0; j < 8; j++) {
                    mt0 = fmaxf(mt0, fmaxf(sacc[rb][j][0], sacc[rb][j][1]));
                    mt1 = fmaxf(mt1, fmaxf(sacc[rb][j][2], sacc[rb][j][3]));
                }
                mt0 = fmaxf(mt0, __shfl_xor_sync(0xffffffffu, mt0, 1));
                mt0 = fmaxf(mt0, __shfl_xor_sync(0xffffffffu, mt0, 2));
                mt1 = fmaxf(mt1, __shfl_xor_sync(0xffffffffu, mt1, 1));
                mt1 = fmaxf(mt1, __shfl_xor_sync(0xffffffffu, mt1, 2));

                const float mn0 = fmaxf(mrow[rb][0], mt0);
                const float mn1 = fmaxf(mrow[rb][1], mt1);
                const float al0 = fexp(mrow[rb][0] - mn0);
                const float al1 = fexp(mrow[rb][1] - mn1);
                mrow[rb][0] = mn0; mrow[rb][1] = mn1;

                float rs0 = 0.0f, rs1 = 0.0f;
#pragma unroll
                for (int j = 0; j < 8; j++) {
                    const float p0 = fexp(sacc[rb][j][0] - mn0);
                    const float p1 = fexp(sacc[rb][j][1] - mn0);
                    const float p2 = fexp(sacc[rb][j][2] - mn1);
                    const float p3 = fexp(sacc[rb][j][3] - mn1);
                    rs0 += p0 + p1;
                    rs1 += p2 + p3;
                    const uint32_t u0 = f2tf32(p0), u1 = f2tf32(p1);
                    const uint32_t u2 = f2tf32(p2), u3 = f2tf32(p3);
                    uint32_t x0 = __shfl_sync(0xffffffffu, u0, srcA);
                    uint32_t x1 = __shfl_sync(0xffffffffu, u1, srcA);
                    uint32_t y0 = __shfl_sync(0xffffffffu, u0, srcA + 2);
                    uint32_t y1 = __shfl_sync(0xffffffffu, u1, srcA + 2);
                    uint32_t x2 = __shfl_sync(0xffffffffu, u2, srcA);
                    uint32_t x3 = __shfl_sync(0xffffffffu, u3, srcA);
                    uint32_t y2 = __shfl_sync(0xffffffffu, u2, srcA + 2);
                    uint32_t y3 = __shfl_sync(0xffffffffu, u3, srcA + 2);
                    pf[rb][j][0] = odd ? x1 : x0;
                    pf[rb][j][2] = odd ? y1 : y0;
                    pf[rb][j][1] = odd ? x3 : x2;
                    pf[rb][j][3] = odd ? y3 : y2;
                }
                rs0 += __shfl_xor_sync(0xffffffffu, rs0, 1);
                rs0 += __shfl_xor_sync(0xffffffffu, rs0, 2);
                rs1 += __shfl_xor_sync(0xffffffffu, rs1, 1);
                rs1 += __shfl_xor_sync(0xffffffffu, rs1, 2);
                lrow[rb][0] = lrow[rb][0] * al0 + rs0;
                lrow[rb][1] = lrow[rb][1] * al1 + rs1;
#pragma unroll
                for (int j = 0; j < 8; j++) {
                    oacc[rb][j][0] *= al0; oacc[rb][j][1] *= al0;
                    oacc[rb][j][2] *= al1; oacc[rb][j][3] *= al1;
                }
            }

            // O += P * V
#pragma unroll
            for (int kb = 0; kb < 8; kb++) {
                uint32_t b[8][2];
#pragma unroll
                for (int j = 0; j < 8; j++) {
                    const int srow = (kb * 8 + tig) * 68 + j * 8 + g;
                    b[j][0] = Vs[srow];
                    b[j][1] = Vs[srow + 4 * 68];
                }
#pragma unroll
                for (int rb = 0; rb < 2; rb++)
#pragma unroll
                    for (int j = 0; j < 8; j++)
                        mma1688(oacc[rb][j], pf[rb][kb], b[j]);
            }
        }
    }

    // finalize, store tf32-rounded into concat layout (B,T,C)
    const int bb = bh >> 4;
    const int hh = bh & 15;
#pragma unroll
    for (int rb = 0; rb < 2; rb++) {
        const float rl0f = 1.0f / lrow[rb][0];
        const float rl1f = 1.0f / lrow[rb][1];
        const int rl0 = wid * 32 + rb * 16 + g;
        const size_t row0 = (size_t)bb * TSEQ + (m0 + rl0);
        const size_t row1 = row0 + 8;
#pragma unroll
        for (int j = 0; j < 8; j++) {
            const int col = hh * DH + j * 8 + 2 * tig;
            float2 v0 = {rtf(oacc[rb][j][0] * rl0f), rtf(oacc[rb][j][1] * rl0f)};
            float2 v1 = {rtf(oacc[rb][j][2] * rl1f), rtf(oacc[rb][j][3] * rl1f)};
            *(float2*)(g_att + row0 * N_EMBD + col) = v0;
            *(float2*)(g_att + row1 * N_EMBD + col) = v1;
        }
    }
}

extern "C" void kernel_launch(void* const* d_in, const int* in_sizes, int n_in,
                              void* d_out, int out_size)
{
    const float* x  = (const float*)d_in[0];
    const float* wq = (const float*)d_in[1];
    const float* wk = (const float*)d_in[2];
    const float* wv = (const float*)d_in[3];
    const float* wp = (const float*)d_in[4];
    const float* bp = (const float*)d_in[5];
    float* out = (float*)d_out;

    cudaFuncSetAttribute(qkv_mma,  cudaFuncAttributeMaxDynamicSharedMemorySize, G_SMEM);
    cudaFuncSetAttribute(proj_mma, cudaFuncAttributeMaxDynamicSharedMemorySize, G_SMEM);
    cudaFuncSetAttribute(flash_mma, cudaFuncAttributeMaxDynamicSharedMemorySize, F_SMEM);

    const int nW4 = NHEAD * N_EMBD * DH / 4;      // 262144
    round_tf32_k<<<(M_TOT * N_EMBD / 4 + 255) / 256, 256>>>((const float4*)x, 0, M_TOT * N_EMBD / 4);
    round_tf32_k<<<(nW4 + 255) / 256, 256>>>((const float4*)wq, 1, nW4);
    round_tf32_k<<<(nW4 + 255) / 256, 256>>>((const float4*)wk, 2, nW4);
    round_tf32_k<<<(nW4 + 255) / 256, 256>>>((const float4*)wv, 3, nW4);
    round_tf32_k<<<(N_EMBD * N_EMBD / 4 + 255) / 256, 256>>>((const float4*)wp, 4, N_EMBD * N_EMBD / 4);

    qkv_mma<<<dim3(3072 / 128, M_TOT / 128), 128, G_SMEM>>>();
    flash_mma<<<dim3(TSEQ / 128, BATCH * NHEAD), 128, F_SMEM>>>();
    proj_mma<<<dim3(N_EMBD / 128, M_TOT / 128), 128, G_SMEM>>>(bp, out);
}